// round 14
// baseline (speedup 1.0000x reference)
#include <cuda_runtime.h>
#include <cuda_fp16.h>
#include <math.h>

#define NN   10000
#define EE   640000
#define TOTE (EE + NN)
#define FULL 0xFFFFFFFFu

// ---------------- scratch (static device globals; no allocation) ----------------
__device__ int   g_deg[NN];          // zero-initialized at load; scan_k re-zeroes after use
__device__ int   g_rowptr[NN + 1];
__device__ int   g_rank[EE];         // per-edge rank within its dst row
__device__ int   g_csr[TOTE];

__device__ __half g_B1t[128 * 128];  // fp16 W1, transposed: Bt[c*128+k] = W[k*128+c]
__device__ __half g_B2t[128 * 128];  // fp16 W2, transposed
__device__ __half g_h1h[NN * 128];   // fp16 h1 = x @ W1 (gather table)
__device__ __half g_o1h[NN * 128];   // fp16 elu(gat1) -> input of gemm2
__device__ __half g_h2h[NN * 128];   // fp16 h2 = o1 @ W2 (gather table)
__device__ float  g_o2[NN * 128];    // fp32 elu(gat2) -> input of head

__device__ float g_as1[NN * 4];
__device__ float g_ad1[NN * 4];
__device__ float g_as2[NN];
__device__ float g_ad2[NN];

__device__ __forceinline__ float lrelu(float v) { return v > 0.f ? v : 0.2f * v; }
__device__ __forceinline__ float elu(float v)   { return v > 0.f ? v : (expf(v) - 1.f); }

// ---- packed f32x2 helpers (sm_103a FFMA2) ----
__device__ __forceinline__ unsigned long long pack2(float lo, float hi) {
    unsigned long long r;
    asm("mov.b64 %0, {%1, %2};" : "=l"(r) : "f"(lo), "f"(hi));
    return r;
}
__device__ __forceinline__ float2 unpack2(unsigned long long v) {
    float2 r;
    asm("mov.b64 {%0, %1}, %2;" : "=f"(r.x), "=f"(r.y) : "l"(v));
    return r;
}
// acc += h2f(u) * qq   (u = __half2 bits, qq = packed (q,q))
__device__ __forceinline__ void ffma2_h2(unsigned long long& acc, unsigned u,
                                         unsigned long long qq) {
    float2 f = __half22float2(*reinterpret_cast<__half2*>(&u));
    unsigned long long t;
    asm("mov.b64 %0, {%1, %2};" : "=l"(t) : "f"(f.x), "f"(f.y));
    asm("fma.rn.f32x2 %0, %1, %2, %0;" : "+l"(acc) : "l"(t), "l"(qq));
}

// ---------------- fused kernel 1: edge histogram (+rank) | weight convert ----------------
__global__ void combo1_k(const int* __restrict__ ei, int e,
                         const float* __restrict__ W1, const float* __restrict__ W2,
                         __half* __restrict__ B1t, __half* __restrict__ B2t, int HB) {
    int t = threadIdx.x;
    if ((int)blockIdx.x < HB) {
        int i = blockIdx.x * 256 + t;
        int q = e >> 2;
        if (i < q) {
            int4 d = ((const int4*)(ei + e))[i];
            int4 r;
            r.x = atomicAdd(&g_deg[d.x], 1);
            r.y = atomicAdd(&g_deg[d.y], 1);
            r.z = atomicAdd(&g_deg[d.z], 1);
            r.w = atomicAdd(&g_deg[d.w], 1);
            ((int4*)g_rank)[i] = r;
        } else {
            int r = (q << 2) + (i - q);         // scalar tail (e % 4 edges)
            if (r < e) g_rank[r] = atomicAdd(&g_deg[ei[e + r]], 1);
        }
    } else {
        int tid = (blockIdx.x - HB) * 256 + t;
        int base = tid * 4;
        if (base < 2 * 128 * 128) {
            const float* W = (base < 128 * 128) ? W1 : W2;
            __half* Bt     = (base < 128 * 128) ? B1t : B2t;
            int off = base & (128 * 128 - 1);
            int c = off >> 7, k = off & 127;
            float v0 = W[(k + 0) * 128 + c];
            float v1 = W[(k + 1) * 128 + c];
            float v2 = W[(k + 2) * 128 + c];
            float v3 = W[(k + 3) * 128 + c];
            __half2 h01 = __floats2half2_rn(v0, v1);
            __half2 h23 = __floats2half2_rn(v2, v3);
            uint2 st;
            st.x = *reinterpret_cast<unsigned*>(&h01);
            st.y = *reinterpret_cast<unsigned*>(&h23);
            *(uint2*)&Bt[c * 128 + k] = st;
        }
    }
}

// single-pass block scan over deg+1 (self loop); writes rowptr, self-loop CSR slot,
// and re-zeroes g_deg for the next launch.
__global__ void scan_k(int n) {
    __shared__ int wsum[32];
    int t = threadIdx.x, lane = t & 31, wid = t >> 5;
    int items = (n + 1023) >> 10;
    int base = t * items;
    int v[16];
    int sum = 0;
    #pragma unroll
    for (int i = 0; i < 16; i++) {
        if (i >= items) break;
        int idx = base + i;
        int x = 0;
        if (idx < n) { x = g_deg[idx] + 1; g_deg[idx] = 0; }
        v[i] = sum;
        sum += x;
    }
    int incl = sum;
    #pragma unroll
    for (int off = 1; off < 32; off <<= 1) {
        int y = __shfl_up_sync(FULL, incl, off);
        if (lane >= off) incl += y;
    }
    if (lane == 31) wsum[wid] = incl;
    __syncthreads();
    if (wid == 0) {
        int wv = wsum[lane];
        int wi = wv;
        #pragma unroll
        for (int off = 1; off < 32; off <<= 1) {
            int y = __shfl_up_sync(FULL, wi, off);
            if (lane >= off) wi += y;
        }
        wsum[lane] = wi - wv;
    }
    __syncthreads();
    int off = wsum[wid] + incl - sum;
    #pragma unroll
    for (int i = 0; i < 16; i++) {
        if (i >= items) break;
        int idx = base + i;
        if (idx < n) {
            int p = off + v[i];
            g_rowptr[idx] = p;
            g_csr[p] = idx;                     // self loop occupies slot 0
        }
    }
    if (t == 1023) g_rowptr[n] = off + sum;
}

// ---- tensor-core GEMM + fused attention-scalar epilogue (device body) ----
template<int HEADS, bool AFP32>
__device__ __forceinline__ void gemm16_body(
        int blk, const void* __restrict__ Avoid, const __half* __restrict__ Bt,
        const float* __restrict__ a_src, const float* __restrict__ a_dst,
        __half* __restrict__ H16,
        float* __restrict__ as_out, float* __restrict__ ad_out, int n) {
    __shared__ __align__(16) __half As[16][136];
    __shared__ __align__(16) float  xs[16][128];
    int row0 = blk * 16;
    int t = threadIdx.x, lane = t & 31, w = t >> 5;

    for (int i = t; i < 16 * 32; i += 128) {
        int r = i >> 5, k4 = (i & 31) << 2;
        int row = row0 + r;
        if (AFP32) {
            const float* Af = (const float*)Avoid;
            float4 v = (row < n) ? *(const float4*)&Af[row * 128 + k4]
                                 : make_float4(0.f, 0.f, 0.f, 0.f);
            *(__half2*)&As[r][k4]     = __floats2half2_rn(v.x, v.y);
            *(__half2*)&As[r][k4 + 2] = __floats2half2_rn(v.z, v.w);
        } else {
            const __half* Ah = (const __half*)Avoid;
            uint2 v = (row < n) ? *(const uint2*)&Ah[row * 128 + k4] : make_uint2(0u, 0u);
            *(uint2*)&As[r][k4] = v;
        }
    }
    __syncthreads();

    int g = lane >> 2, t4 = lane & 3;
    float c[4][4];
    #pragma unroll
    for (int nt = 0; nt < 4; nt++)
        #pragma unroll
        for (int i = 0; i < 4; i++) c[nt][i] = 0.f;

    #pragma unroll
    for (int kc = 0; kc < 128; kc += 16) {
        unsigned a0 = *(const unsigned*)&As[g][kc + t4 * 2];
        unsigned a1 = *(const unsigned*)&As[g + 8][kc + t4 * 2];
        unsigned a2 = *(const unsigned*)&As[g][kc + 8 + t4 * 2];
        unsigned a3 = *(const unsigned*)&As[g + 8][kc + 8 + t4 * 2];
        #pragma unroll
        for (int nt = 0; nt < 4; nt++) {
            int col = (w * 4 + nt) * 8 + g;
            unsigned b0 = *(const unsigned*)&Bt[col * 128 + kc + t4 * 2];
            unsigned b1 = *(const unsigned*)&Bt[col * 128 + kc + 8 + t4 * 2];
            asm volatile(
                "mma.sync.aligned.m16n8k16.row.col.f32.f16.f16.f32 "
                "{%0,%1,%2,%3}, {%4,%5,%6,%7}, {%8,%9}, {%0,%1,%2,%3};"
                : "+f"(c[nt][0]), "+f"(c[nt][1]), "+f"(c[nt][2]), "+f"(c[nt][3])
                : "r"(a0), "r"(a1), "r"(a2), "r"(a3), "r"(b0), "r"(b1));
        }
    }

    __syncthreads();
    #pragma unroll
    for (int nt = 0; nt < 4; nt++) {
        int colb = (w * 4 + nt) * 8 + t4 * 2;
        int r0 = row0 + g, r1 = row0 + g + 8;
        if (r0 < n) {
            *(__half2*)&H16[r0 * 128 + colb] = __floats2half2_rn(c[nt][0], c[nt][1]);
            xs[g][colb]     = c[nt][0];
            xs[g][colb + 1] = c[nt][1];
        }
        if (r1 < n) {
            *(__half2*)&H16[r1 * 128 + colb] = __floats2half2_rn(c[nt][2], c[nt][3]);
            xs[g + 8][colb]     = c[nt][2];
            xs[g + 8][colb + 1] = c[nt][3];
        }
    }
    __syncthreads();

    float4 sv = *(const float4*)&a_src[lane * 4];
    float4 dv = *(const float4*)&a_dst[lane * 4];
    #pragma unroll
    for (int r4 = 0; r4 < 4; r4++) {
        int r = w * 4 + r4;
        float4 hv = *(const float4*)&xs[r][lane * 4];
        float ps = hv.x * sv.x + hv.y * sv.y + hv.z * sv.z + hv.w * sv.w;
        float pd = hv.x * dv.x + hv.y * dv.y + hv.z * dv.z + hv.w * dv.w;
        if (HEADS == 4) {
            #pragma unroll
            for (int off = 1; off < 8; off <<= 1) {
                ps += __shfl_xor_sync(FULL, ps, off);
                pd += __shfl_xor_sync(FULL, pd, off);
            }
            int row = row0 + r;
            if (row < n && (lane & 7) == 0) {
                as_out[row * 4 + (lane >> 3)] = ps;
                ad_out[row * 4 + (lane >> 3)] = pd;
            }
        } else {
            #pragma unroll
            for (int off = 1; off < 32; off <<= 1) {
                ps += __shfl_xor_sync(FULL, ps, off);
                pd += __shfl_xor_sync(FULL, pd, off);
            }
            int row = row0 + r;
            if (row < n && lane == 0) { as_out[row] = ps; ad_out[row] = pd; }
        }
    }
}

// ---------------- fused kernel 2: CSR fill | layer-1 GEMM ----------------
__global__ void combo2_k(const int* __restrict__ ei, int e,
                         const float* __restrict__ x, const __half* __restrict__ B1t,
                         const float* __restrict__ a_src, const float* __restrict__ a_dst,
                         __half* __restrict__ H16,
                         float* __restrict__ as_out, float* __restrict__ ad_out,
                         int n, int FB) {
    if ((int)blockIdx.x < FB) {
        int i = blockIdx.x * 128 + threadIdx.x;
        int q = e >> 2;
        if (i < q) {
            int4 s = ((const int4*)ei)[i];
            int4 d = ((const int4*)(ei + e))[i];
            int4 r = ((const int4*)g_rank)[i];
            g_csr[g_rowptr[d.x] + 1 + r.x] = s.x;
            g_csr[g_rowptr[d.y] + 1 + r.y] = s.y;
            g_csr[g_rowptr[d.z] + 1 + r.z] = s.z;
            g_csr[g_rowptr[d.w] + 1 + r.w] = s.w;
        } else {
            int r = i - q;
            int tail = e & 3;
            if (r < tail) {
                int idx = (q << 2) + r;
                g_csr[g_rowptr[ei[e + idx]] + 1 + g_rank[idx]] = ei[idx];
            }
        }
    } else {
        gemm16_body<4, true>(blockIdx.x - FB, x, B1t, a_src, a_dst,
                             H16, as_out, ad_out, n);
    }
}

__global__ void gemm2_k(const __half* __restrict__ A, const __half* __restrict__ Bt,
                        const float* __restrict__ a_src, const float* __restrict__ a_dst,
                        __half* __restrict__ H16,
                        float* __restrict__ as_out, float* __restrict__ ad_out, int n) {
    gemm16_body<1, false>(blockIdx.x, A, Bt, a_src, a_dst, H16, as_out, ad_out, n);
}

// ---------------- GAT aggregation, layer 1 (4 heads) ----------------
// half-warp edge-pairing + 2-edge ILP + packed f32x2 FMA accumulators.
__global__ void __launch_bounds__(256, 6) att1_k(const __half* __restrict__ h,
                                                 const float* __restrict__ b,
                                                 __half* __restrict__ out, int n) {
    __shared__ __align__(16) float2 sm_hp[8][4][34];  // [warp][head][edge]; 34 -> 272B rows
    int node = (blockIdx.x * blockDim.x + threadIdx.x) >> 5;
    int lane = threadIdx.x & 31;
    int ws = (threadIdx.x >> 5) & 7;
    if (node >= n) return;
    int s0 = g_rowptr[node], s1 = g_rowptr[node + 1];

    float4 adv = *(const float4*)&g_ad1[node * 4];
    int hl = lane & 15, half = lane >> 4;
    int head_g = hl >> 2;                  // head of the 8 dims this lane gathers
    unsigned long long acc01 = 0, acc23 = 0, acc45 = 0, acc67 = 0;
    float z0 = 0.f, z1 = 0.f, z2 = 0.f, z3 = 0.f;

    for (int base = s0; base < s1; base += 32) {
        int j = base + lane;
        int s = 0;
        float4 p = make_float4(0.f, 0.f, 0.f, 0.f);
        if (j < s1) {
            s = __ldg(&g_csr[j]);
            float4 asv = *(const float4*)&g_as1[s * 4];
            p.x = __expf(lrelu(asv.x + adv.x));
            p.y = __expf(lrelu(asv.y + adv.y));
            p.z = __expf(lrelu(asv.z + adv.z));
            p.w = __expf(lrelu(asv.w + adv.w));
            z0 += p.x; z1 += p.y; z2 += p.z; z3 += p.w;
        }
        __syncwarp();
        float fs = __int_as_float(s);
        sm_hp[ws][0][lane] = make_float2(fs, p.x);
        sm_hp[ws][1][lane] = make_float2(fs, p.y);
        sm_hp[ws][2][lane] = make_float2(fs, p.z);
        sm_hp[ws][3][lane] = make_float2(fs, p.w);
        __syncwarp();
        int cnt = min(32, s1 - base);
        int jb = half << 4;
        int je = min(cnt, jb + 16);
        int jj = jb;
        #pragma unroll 2
        for (; jj + 1 < je; jj += 2) {
            float4 sp = *(const float4*)&sm_hp[ws][head_g][jj];   // two pairs
            int   sa = __float_as_int(sp.x);
            int   sb = __float_as_int(sp.z);
            unsigned long long qa = pack2(sp.y, sp.y);
            unsigned long long qb = pack2(sp.w, sp.w);
            uint4 ua = *(const uint4*)&h[sa * 128 + (hl << 3)];
            uint4 ub = *(const uint4*)&h[sb * 128 + (hl << 3)];
            ffma2_h2(acc01, ua.x, qa); ffma2_h2(acc23, ua.y, qa);
            ffma2_h2(acc45, ua.z, qa); ffma2_h2(acc67, ua.w, qa);
            ffma2_h2(acc01, ub.x, qb); ffma2_h2(acc23, ub.y, qb);
            ffma2_h2(acc45, ub.z, qb); ffma2_h2(acc67, ub.w, qb);
        }
        if (jj < je) {
            float2 sp = sm_hp[ws][head_g][jj];
            int   sa = __float_as_int(sp.x);
            unsigned long long qa = pack2(sp.y, sp.y);
            uint4 ua = *(const uint4*)&h[sa * 128 + (hl << 3)];
            ffma2_h2(acc01, ua.x, qa); ffma2_h2(acc23, ua.y, qa);
            ffma2_h2(acc45, ua.z, qa); ffma2_h2(acc67, ua.w, qa);
        }
    }
    float2 a01 = unpack2(acc01), a23 = unpack2(acc23);
    float2 a45 = unpack2(acc45), a67 = unpack2(acc67);
    float acc[8] = {a01.x, a01.y, a23.x, a23.y, a45.x, a45.y, a67.x, a67.y};
    // merge the two halves
    #pragma unroll
    for (int i = 0; i < 8; i++) acc[i] += __shfl_xor_sync(FULL, acc[i], 16);
    #pragma unroll
    for (int off = 16; off; off >>= 1) {
        z0 += __shfl_xor_sync(FULL, z0, off);
        z1 += __shfl_xor_sync(FULL, z1, off);
        z2 += __shfl_xor_sync(FULL, z2, off);
        z3 += __shfl_xor_sync(FULL, z3, off);
    }
    if (half == 0) {
        float z = head_g == 0 ? z0 : head_g == 1 ? z1 : head_g == 2 ? z2 : z3;
        float inv = 1.f / z;
        int c = hl << 3;
        float4 b0 = *(const float4*)&b[c];
        float4 b1 = *(const float4*)&b[c + 4];
        __half2 v0 = __floats2half2_rn(elu(acc[0] * inv + b0.x), elu(acc[1] * inv + b0.y));
        __half2 v1 = __floats2half2_rn(elu(acc[2] * inv + b0.z), elu(acc[3] * inv + b0.w));
        __half2 v2 = __floats2half2_rn(elu(acc[4] * inv + b1.x), elu(acc[5] * inv + b1.y));
        __half2 v3 = __floats2half2_rn(elu(acc[6] * inv + b1.z), elu(acc[7] * inv + b1.w));
        uint4 st;
        st.x = *reinterpret_cast<unsigned*>(&v0);
        st.y = *reinterpret_cast<unsigned*>(&v1);
        st.z = *reinterpret_cast<unsigned*>(&v2);
        st.w = *reinterpret_cast<unsigned*>(&v3);
        *(uint4*)&out[node * 128 + c] = st;
    }
}

// ---------------- GAT aggregation, layer 2 (1 head) ----------------
__global__ void __launch_bounds__(256, 6) att2_k(const __half* __restrict__ h,
                                                 const float* __restrict__ b,
                                                 float* __restrict__ out, int n) {
    __shared__ __align__(16) float2 sm2[8][34];
    int node = (blockIdx.x * blockDim.x + threadIdx.x) >> 5;
    int lane = threadIdx.x & 31;
    int ws = (threadIdx.x >> 5) & 7;
    if (node >= n) return;
    int s0 = g_rowptr[node], s1 = g_rowptr[node + 1];

    float ad = g_ad2[node];
    int hl = lane & 15, half = lane >> 4;
    unsigned long long acc01 = 0, acc23 = 0, acc45 = 0, acc67 = 0;
    float z = 0.f;

    for (int base = s0; base < s1; base += 32) {
        int j = base + lane;
        int s = 0; float p = 0.f;
        if (j < s1) {
            s = __ldg(&g_csr[j]);
            p = __expf(lrelu(g_as2[s] + ad));
            z += p;
        }
        __syncwarp();
        sm2[ws][lane] = make_float2(__int_as_float(s), p);
        __syncwarp();
        int cnt = min(32, s1 - base);
        int jb = half << 4;
        int je = min(cnt, jb + 16);
        int jj = jb;
        #pragma unroll 2
        for (; jj + 1 < je; jj += 2) {
            float4 sp = *(const float4*)&sm2[ws][jj];
            int   sa = __float_as_int(sp.x);
            int   sb = __float_as_int(sp.z);
            unsigned long long qa = pack2(sp.y, sp.y);
            unsigned long long qb = pack2(sp.w, sp.w);
            uint4 ua = *(const uint4*)&h[sa * 128 + (hl << 3)];
            uint4 ub = *(const uint4*)&h[sb * 128 + (hl << 3)];
            ffma2_h2(acc01, ua.x, qa); ffma2_h2(acc23, ua.y, qa);
            ffma2_h2(acc45, ua.z, qa); ffma2_h2(acc67, ua.w, qa);
            ffma2_h2(acc01, ub.x, qb); ffma2_h2(acc23, ub.y, qb);
            ffma2_h2(acc45, ub.z, qb); ffma2_h2(acc67, ub.w, qb);
        }
        if (jj < je) {
            float2 sp = sm2[ws][jj];
            int   sa = __float_as_int(sp.x);
            unsigned long long qa = pack2(sp.y, sp.y);
            uint4 ua = *(const uint4*)&h[sa * 128 + (hl << 3)];
            ffma2_h2(acc01, ua.x, qa); ffma2_h2(acc23, ua.y, qa);
            ffma2_h2(acc45, ua.z, qa); ffma2_h2(acc67, ua.w, qa);
        }
    }
    float2 a01 = unpack2(acc01), a23 = unpack2(acc23);
    float2 a45 = unpack2(acc45), a67 = unpack2(acc67);
    float acc[8] = {a01.x, a01.y, a23.x, a23.y, a45.x, a45.y, a67.x, a67.y};
    #pragma unroll
    for (int i = 0; i < 8; i++) acc[i] += __shfl_xor_sync(FULL, acc[i], 16);
    #pragma unroll
    for (int off = 16; off; off >>= 1)
        z += __shfl_xor_sync(FULL, z, off);
    if (half == 0) {
        float inv = 1.f / z;
        int c = hl << 3;
        float4 b0 = *(const float4*)&b[c];
        float4 b1 = *(const float4*)&b[c + 4];
        float4 o0, o1;
        o0.x = elu(acc[0] * inv + b0.x);
        o0.y = elu(acc[1] * inv + b0.y);
        o0.z = elu(acc[2] * inv + b0.z);
        o0.w = elu(acc[3] * inv + b0.w);
        o1.x = elu(acc[4] * inv + b1.x);
        o1.y = elu(acc[5] * inv + b1.y);
        o1.z = elu(acc[6] * inv + b1.z);
        o1.w = elu(acc[7] * inv + b1.w);
        *(float4*)&out[node * 128 + c]     = o0;
        *(float4*)&out[node * 128 + c + 4] = o1;
    }
}

// ---------------- final linear head: [n,128] @ [128,40] + b ----------------
__global__ void head_k(const float* __restrict__ A, const float* __restrict__ W,
                       const float* __restrict__ b, float* __restrict__ out, int n) {
    int i = blockIdx.x * blockDim.x + threadIdx.x;
    if (i >= n * 40) return;
    int row = i / 40, c = i - row * 40;
    const float* xr = &A[row * 128];
    float acc = b[c];
    #pragma unroll 8
    for (int k = 0; k < 128; k++)
        acc += xr[k] * __ldg(&W[k * 40 + c]);
    out[i] = acc;
}

// ---------------- launch ----------------
extern "C" void kernel_launch(void* const* d_in, const int* in_sizes, int n_in,
                              void* d_out, int out_size) {
    const float* x   = (const float*)d_in[0];
    const int*   ei  = (const int*)  d_in[1];
    const float* W1  = (const float*)d_in[2];
    const float* as1 = (const float*)d_in[3];
    const float* ad1 = (const float*)d_in[4];
    const float* b1  = (const float*)d_in[5];
    const float* W2  = (const float*)d_in[6];
    const float* as2 = (const float*)d_in[7];
    const float* ad2 = (const float*)d_in[8];
    const float* b2  = (const float*)d_in[9];
    const float* Wl  = (const float*)d_in[10];
    const float* bl  = (const float*)d_in[11];
    float* out = (float*)d_out;

    const int n = in_sizes[0] / 128;   // 10000
    const int e = in_sizes[1] / 2;     // 640000

    __half *B1t, *B2t, *h1h, *h2h, *o1h;
    float *o2, *pas1, *pad1, *pas2, *pad2;
    cudaGetSymbolAddress((void**)&B1t, g_B1t);
    cudaGetSymbolAddress((void**)&B2t, g_B2t);
    cudaGetSymbolAddress((void**)&h1h, g_h1h);
    cudaGetSymbolAddress((void**)&h2h, g_h2h);
    cudaGetSymbolAddress((void**)&o1h, g_o1h);
    cudaGetSymbolAddress((void**)&o2,  g_o2);
    cudaGetSymbolAddress((void**)&pas1, g_as1);
    cudaGetSymbolAddress((void**)&pad1, g_ad1);
    cudaGetSymbolAddress((void**)&pas2, g_as2);
    cudaGetSymbolAddress((void**)&pad2, g_ad2);

    int q = e >> 2, tail = e & 3;

    // K1: hist + weight convert (independent; co-scheduled)
    int HB = (q + tail + 255) / 256;
    int WB = (2 * 128 * 128 / 4 + 255) / 256;
    combo1_k<<<HB + WB, 256>>>(ei, e, W1, W2, B1t, B2t, HB);

    // K2: scan (rowptr + self-loop slots + deg reset)
    scan_k<<<1, 1024>>>(n);

    // K3: fill + layer-1 GEMM (independent; co-scheduled)
    int FB = (q + tail + 127) / 128;
    int GB = (n + 15) / 16;
    combo2_k<<<FB + GB, 128>>>(ei, e, x, B1t, as1, ad1, h1h, pas1, pad1, n, FB);

    // K4: layer-1 aggregation
    att1_k<<<(n * 32 + 255) / 256, 256>>>(h1h, b1, o1h, n);

    // K5: layer-2 GEMM
    gemm2_k<<<(n + 15) / 16, 128>>>(o1h, B2t, as2, ad2, h2h, pas2, pad2, n);

    // K6: layer-2 aggregation
    att2_k<<<(n * 32 + 255) / 256, 256>>>(h2h, b2, o2, n);

    // K7: head
    head_k<<<(n * 40 + 255) / 256, 256>>>(o2, Wl, bl, out, n);
}

// round 15
// speedup vs baseline: 1.0290x; 1.0290x over previous
#include <cuda_runtime.h>
#include <cuda_fp16.h>
#include <math.h>

#define NN   10000
#define EE   640000
#define TOTE (EE + NN)
#define FULL 0xFFFFFFFFu

// ---------------- scratch (static device globals; no allocation) ----------------
__device__ int   g_deg[NN];          // zero-initialized at load; scan_k re-zeroes after use
__device__ int   g_rowptr[NN + 1];
__device__ int   g_rank[EE];         // per-edge rank within its dst row
__device__ int   g_csr[TOTE];

__device__ __half g_B1t[128 * 128];  // fp16 W1, transposed: Bt[c*128+k] = W[k*128+c]
__device__ __half g_B2t[128 * 128];  // fp16 W2, transposed
__device__ __half g_h1h[NN * 128];   // fp16 h1 = x @ W1 (gather table)
__device__ __half g_o1h[NN * 128];   // fp16 elu(gat1) -> input of gemm2
__device__ __half g_h2h[NN * 128];   // fp16 h2 = o1 @ W2 (gather table)
__device__ float  g_o2[NN * 128];    // fp32 elu(gat2) -> input of head

__device__ float g_as1[NN * 4];
__device__ float g_ad1[NN * 4];
__device__ float g_as2[NN];
__device__ float g_ad2[NN];

__device__ __forceinline__ float lrelu(float v) { return v > 0.f ? v : 0.2f * v; }
__device__ __forceinline__ float elu(float v)   { return v > 0.f ? v : (expf(v) - 1.f); }

__device__ __forceinline__ unsigned h2bits(__half2 v) {
    return *reinterpret_cast<unsigned*>(&v);
}
__device__ __forceinline__ __half2 bits2h(unsigned v) {
    return *reinterpret_cast<__half2*>(&v);
}

// ---------------- fused kernel 1: edge histogram (+rank) | weight convert ----------------
__global__ void combo1_k(const int* __restrict__ ei, int e,
                         const float* __restrict__ W1, const float* __restrict__ W2,
                         __half* __restrict__ B1t, __half* __restrict__ B2t, int HB) {
    int t = threadIdx.x;
    if ((int)blockIdx.x < HB) {
        int i = blockIdx.x * 256 + t;
        int q = e >> 2;
        if (i < q) {
            int4 d = ((const int4*)(ei + e))[i];
            int4 r;
            r.x = atomicAdd(&g_deg[d.x], 1);
            r.y = atomicAdd(&g_deg[d.y], 1);
            r.z = atomicAdd(&g_deg[d.z], 1);
            r.w = atomicAdd(&g_deg[d.w], 1);
            ((int4*)g_rank)[i] = r;
        } else {
            int r = (q << 2) + (i - q);         // scalar tail (e % 4 edges)
            if (r < e) g_rank[r] = atomicAdd(&g_deg[ei[e + r]], 1);
        }
    } else {
        int tid = (blockIdx.x - HB) * 256 + t;
        int base = tid * 4;
        if (base < 2 * 128 * 128) {
            const float* W = (base < 128 * 128) ? W1 : W2;
            __half* Bt     = (base < 128 * 128) ? B1t : B2t;
            int off = base & (128 * 128 - 1);
            int c = off >> 7, k = off & 127;
            float v0 = W[(k + 0) * 128 + c];
            float v1 = W[(k + 1) * 128 + c];
            float v2 = W[(k + 2) * 128 + c];
            float v3 = W[(k + 3) * 128 + c];
            __half2 h01 = __floats2half2_rn(v0, v1);
            __half2 h23 = __floats2half2_rn(v2, v3);
            uint2 st;
            st.x = h2bits(h01);
            st.y = h2bits(h23);
            *(uint2*)&Bt[c * 128 + k] = st;
        }
    }
}

// single-pass block scan over deg+1 (self loop); writes rowptr, self-loop CSR slot,
// and re-zeroes g_deg for the next launch.
__global__ void scan_k(int n) {
    __shared__ int wsum[32];
    int t = threadIdx.x, lane = t & 31, wid = t >> 5;
    int items = (n + 1023) >> 10;
    int base = t * items;
    int v[16];
    int sum = 0;
    #pragma unroll
    for (int i = 0; i < 16; i++) {
        if (i >= items) break;
        int idx = base + i;
        int x = 0;
        if (idx < n) { x = g_deg[idx] + 1; g_deg[idx] = 0; }
        v[i] = sum;
        sum += x;
    }
    int incl = sum;
    #pragma unroll
    for (int off = 1; off < 32; off <<= 1) {
        int y = __shfl_up_sync(FULL, incl, off);
        if (lane >= off) incl += y;
    }
    if (lane == 31) wsum[wid] = incl;
    __syncthreads();
    if (wid == 0) {
        int wv = wsum[lane];
        int wi = wv;
        #pragma unroll
        for (int off = 1; off < 32; off <<= 1) {
            int y = __shfl_up_sync(FULL, wi, off);
            if (lane >= off) wi += y;
        }
        wsum[lane] = wi - wv;
    }
    __syncthreads();
    int off = wsum[wid] + incl - sum;
    #pragma unroll
    for (int i = 0; i < 16; i++) {
        if (i >= items) break;
        int idx = base + i;
        if (idx < n) {
            int p = off + v[i];
            g_rowptr[idx] = p;
            g_csr[p] = idx;                     // self loop occupies slot 0
        }
    }
    if (t == 1023) g_rowptr[n] = off + sum;
}

// ---- tensor-core GEMM + fused attention-scalar epilogue (device body) ----
template<int HEADS, bool AFP32>
__device__ __forceinline__ void gemm16_body(
        int blk, const void* __restrict__ Avoid, const __half* __restrict__ Bt,
        const float* __restrict__ a_src, const float* __restrict__ a_dst,
        __half* __restrict__ H16,
        float* __restrict__ as_out, float* __restrict__ ad_out, int n) {
    __shared__ __align__(16) __half As[16][136];
    __shared__ __align__(16) float  xs[16][128];
    int row0 = blk * 16;
    int t = threadIdx.x, lane = t & 31, w = t >> 5;

    for (int i = t; i < 16 * 32; i += 128) {
        int r = i >> 5, k4 = (i & 31) << 2;
        int row = row0 + r;
        if (AFP32) {
            const float* Af = (const float*)Avoid;
            float4 v = (row < n) ? *(const float4*)&Af[row * 128 + k4]
                                 : make_float4(0.f, 0.f, 0.f, 0.f);
            *(__half2*)&As[r][k4]     = __floats2half2_rn(v.x, v.y);
            *(__half2*)&As[r][k4 + 2] = __floats2half2_rn(v.z, v.w);
        } else {
            const __half* Ah = (const __half*)Avoid;
            uint2 v = (row < n) ? *(const uint2*)&Ah[row * 128 + k4] : make_uint2(0u, 0u);
            *(uint2*)&As[r][k4] = v;
        }
    }
    __syncthreads();

    int g = lane >> 2, t4 = lane & 3;
    float c[4][4];
    #pragma unroll
    for (int nt = 0; nt < 4; nt++)
        #pragma unroll
        for (int i = 0; i < 4; i++) c[nt][i] = 0.f;

    #pragma unroll
    for (int kc = 0; kc < 128; kc += 16) {
        unsigned a0 = *(const unsigned*)&As[g][kc + t4 * 2];
        unsigned a1 = *(const unsigned*)&As[g + 8][kc + t4 * 2];
        unsigned a2 = *(const unsigned*)&As[g][kc + 8 + t4 * 2];
        unsigned a3 = *(const unsigned*)&As[g + 8][kc + 8 + t4 * 2];
        #pragma unroll
        for (int nt = 0; nt < 4; nt++) {
            int col = (w * 4 + nt) * 8 + g;
            unsigned b0 = *(const unsigned*)&Bt[col * 128 + kc + t4 * 2];
            unsigned b1 = *(const unsigned*)&Bt[col * 128 + kc + 8 + t4 * 2];
            asm volatile(
                "mma.sync.aligned.m16n8k16.row.col.f32.f16.f16.f32 "
                "{%0,%1,%2,%3}, {%4,%5,%6,%7}, {%8,%9}, {%0,%1,%2,%3};"
                : "+f"(c[nt][0]), "+f"(c[nt][1]), "+f"(c[nt][2]), "+f"(c[nt][3])
                : "r"(a0), "r"(a1), "r"(a2), "r"(a3), "r"(b0), "r"(b1));
        }
    }

    __syncthreads();
    #pragma unroll
    for (int nt = 0; nt < 4; nt++) {
        int colb = (w * 4 + nt) * 8 + t4 * 2;
        int r0 = row0 + g, r1 = row0 + g + 8;
        if (r0 < n) {
            *(__half2*)&H16[r0 * 128 + colb] = __floats2half2_rn(c[nt][0], c[nt][1]);
            xs[g][colb]     = c[nt][0];
            xs[g][colb + 1] = c[nt][1];
        }
        if (r1 < n) {
            *(__half2*)&H16[r1 * 128 + colb] = __floats2half2_rn(c[nt][2], c[nt][3]);
            xs[g + 8][colb]     = c[nt][2];
            xs[g + 8][colb + 1] = c[nt][3];
        }
    }
    __syncthreads();

    float4 sv = *(const float4*)&a_src[lane * 4];
    float4 dv = *(const float4*)&a_dst[lane * 4];
    #pragma unroll
    for (int r4 = 0; r4 < 4; r4++) {
        int r = w * 4 + r4;
        float4 hv = *(const float4*)&xs[r][lane * 4];
        float ps = hv.x * sv.x + hv.y * sv.y + hv.z * sv.z + hv.w * sv.w;
        float pd = hv.x * dv.x + hv.y * dv.y + hv.z * dv.z + hv.w * dv.w;
        if (HEADS == 4) {
            #pragma unroll
            for (int off = 1; off < 8; off <<= 1) {
                ps += __shfl_xor_sync(FULL, ps, off);
                pd += __shfl_xor_sync(FULL, pd, off);
            }
            int row = row0 + r;
            if (row < n && (lane & 7) == 0) {
                as_out[row * 4 + (lane >> 3)] = ps;
                ad_out[row * 4 + (lane >> 3)] = pd;
            }
        } else {
            #pragma unroll
            for (int off = 1; off < 32; off <<= 1) {
                ps += __shfl_xor_sync(FULL, ps, off);
                pd += __shfl_xor_sync(FULL, pd, off);
            }
            int row = row0 + r;
            if (row < n && lane == 0) { as_out[row] = ps; ad_out[row] = pd; }
        }
    }
}

// ---------------- fused kernel 2: CSR fill | layer-1 GEMM ----------------
__global__ void combo2_k(const int* __restrict__ ei, int e,
                         const float* __restrict__ x, const __half* __restrict__ B1t,
                         const float* __restrict__ a_src, const float* __restrict__ a_dst,
                         __half* __restrict__ H16,
                         float* __restrict__ as_out, float* __restrict__ ad_out,
                         int n, int FB) {
    if ((int)blockIdx.x < FB) {
        int i = blockIdx.x * 128 + threadIdx.x;
        int q = e >> 2;
        if (i < q) {
            int4 s = ((const int4*)ei)[i];
            int4 d = ((const int4*)(ei + e))[i];
            int4 r = ((const int4*)g_rank)[i];
            g_csr[g_rowptr[d.x] + 1 + r.x] = s.x;
            g_csr[g_rowptr[d.y] + 1 + r.y] = s.y;
            g_csr[g_rowptr[d.z] + 1 + r.z] = s.z;
            g_csr[g_rowptr[d.w] + 1 + r.w] = s.w;
        } else {
            int r = i - q;
            int tail = e & 3;
            if (r < tail) {
                int idx = (q << 2) + r;
                g_csr[g_rowptr[ei[e + idx]] + 1 + g_rank[idx]] = ei[idx];
            }
        }
    } else {
        gemm16_body<4, true>(blockIdx.x - FB, x, B1t, a_src, a_dst,
                             H16, as_out, ad_out, n);
    }
}

__global__ void gemm2_k(const __half* __restrict__ A, const __half* __restrict__ Bt,
                        const float* __restrict__ a_src, const float* __restrict__ a_dst,
                        __half* __restrict__ H16,
                        float* __restrict__ as_out, float* __restrict__ ad_out, int n) {
    gemm16_body<1, false>(blockIdx.x, A, Bt, a_src, a_dst, H16, as_out, ad_out, n);
}

// ---------------- GAT aggregation, layer 1 (4 heads) ----------------
// half-warp edge-pairing + 2-edge ILP + HFMA2 window accumulation:
// q staged as half2(p,p); per edge 4 HFMA2 into half2 accs, flushed to fp32
// once per 32-edge window (<=16 edges per half-warp; sums bounded ~6e3 << 65504).
__global__ void __launch_bounds__(256, 6) att1_k(const __half* __restrict__ h,
                                                 const float* __restrict__ b,
                                                 __half* __restrict__ out, int n) {
    __shared__ __align__(16) uint2 smq[8][4][34];  // [warp][head][edge] = {src, half2(p,p)}
    int node = (blockIdx.x * blockDim.x + threadIdx.x) >> 5;
    int lane = threadIdx.x & 31;
    int ws = (threadIdx.x >> 5) & 7;
    if (node >= n) return;
    int s0 = g_rowptr[node], s1 = g_rowptr[node + 1];

    float4 adv = *(const float4*)&g_ad1[node * 4];
    int hl = lane & 15, half = lane >> 4;
    int head_g = hl >> 2;                  // head of the 8 dims this lane gathers
    float acc[8];
    #pragma unroll
    for (int i = 0; i < 8; i++) acc[i] = 0.f;
    float z0 = 0.f, z1 = 0.f, z2 = 0.f, z3 = 0.f;

    for (int base = s0; base < s1; base += 32) {
        int j = base + lane;
        int s = 0;
        float p0 = 0.f, p1 = 0.f, p2 = 0.f, p3 = 0.f;
        if (j < s1) {
            s = __ldg(&g_csr[j]);
            float4 asv = *(const float4*)&g_as1[s * 4];
            p0 = __expf(lrelu(asv.x + adv.x));
            p1 = __expf(lrelu(asv.y + adv.y));
            p2 = __expf(lrelu(asv.z + adv.z));
            p3 = __expf(lrelu(asv.w + adv.w));
            z0 += p0; z1 += p1; z2 += p2; z3 += p3;
        }
        __syncwarp();
        smq[ws][0][lane] = make_uint2(s, h2bits(__floats2half2_rn(p0, p0)));
        smq[ws][1][lane] = make_uint2(s, h2bits(__floats2half2_rn(p1, p1)));
        smq[ws][2][lane] = make_uint2(s, h2bits(__floats2half2_rn(p2, p2)));
        smq[ws][3][lane] = make_uint2(s, h2bits(__floats2half2_rn(p3, p3)));
        __syncwarp();
        int cnt = min(32, s1 - base);
        int jb = half << 4;
        int je = min(cnt, jb + 16);
        int jj = jb;
        __half2 ha0 = bits2h(0u), ha1 = bits2h(0u), ha2 = bits2h(0u), ha3 = bits2h(0u);
        #pragma unroll 2
        for (; jj + 1 < je; jj += 2) {
            uint4 sp = *(const uint4*)&smq[ws][head_g][jj];   // two edges
            int sa = (int)sp.x;  __half2 qa = bits2h(sp.y);
            int sb = (int)sp.z;  __half2 qb = bits2h(sp.w);
            uint4 ua = *(const uint4*)&h[sa * 128 + (hl << 3)];
            uint4 ub = *(const uint4*)&h[sb * 128 + (hl << 3)];
            ha0 = __hfma2(bits2h(ua.x), qa, ha0);
            ha1 = __hfma2(bits2h(ua.y), qa, ha1);
            ha2 = __hfma2(bits2h(ua.z), qa, ha2);
            ha3 = __hfma2(bits2h(ua.w), qa, ha3);
            ha0 = __hfma2(bits2h(ub.x), qb, ha0);
            ha1 = __hfma2(bits2h(ub.y), qb, ha1);
            ha2 = __hfma2(bits2h(ub.z), qb, ha2);
            ha3 = __hfma2(bits2h(ub.w), qb, ha3);
        }
        if (jj < je) {
            uint2 sp = smq[ws][head_g][jj];
            int sa = (int)sp.x;  __half2 qa = bits2h(sp.y);
            uint4 ua = *(const uint4*)&h[sa * 128 + (hl << 3)];
            ha0 = __hfma2(bits2h(ua.x), qa, ha0);
            ha1 = __hfma2(bits2h(ua.y), qa, ha1);
            ha2 = __hfma2(bits2h(ua.z), qa, ha2);
            ha3 = __hfma2(bits2h(ua.w), qa, ha3);
        }
        // flush window to fp32
        float2 f0 = __half22float2(ha0);
        float2 f1 = __half22float2(ha1);
        float2 f2 = __half22float2(ha2);
        float2 f3 = __half22float2(ha3);
        acc[0] += f0.x; acc[1] += f0.y;
        acc[2] += f1.x; acc[3] += f1.y;
        acc[4] += f2.x; acc[5] += f2.y;
        acc[6] += f3.x; acc[7] += f3.y;
    }
    // merge the two halves
    #pragma unroll
    for (int i = 0; i < 8; i++) acc[i] += __shfl_xor_sync(FULL, acc[i], 16);
    #pragma unroll
    for (int off = 16; off; off >>= 1) {
        z0 += __shfl_xor_sync(FULL, z0, off);
        z1 += __shfl_xor_sync(FULL, z1, off);
        z2 += __shfl_xor_sync(FULL, z2, off);
        z3 += __shfl_xor_sync(FULL, z3, off);
    }
    if (half == 0) {
        float z = head_g == 0 ? z0 : head_g == 1 ? z1 : head_g == 2 ? z2 : z3;
        float inv = 1.f / z;
        int c = hl << 3;
        float4 b0 = *(const float4*)&b[c];
        float4 b1 = *(const float4*)&b[c + 4];
        __half2 v0 = __floats2half2_rn(elu(acc[0] * inv + b0.x), elu(acc[1] * inv + b0.y));
        __half2 v1 = __floats2half2_rn(elu(acc[2] * inv + b0.z), elu(acc[3] * inv + b0.w));
        __half2 v2 = __floats2half2_rn(elu(acc[4] * inv + b1.x), elu(acc[5] * inv + b1.y));
        __half2 v3 = __floats2half2_rn(elu(acc[6] * inv + b1.z), elu(acc[7] * inv + b1.w));
        uint4 st;
        st.x = h2bits(v0);
        st.y = h2bits(v1);
        st.z = h2bits(v2);
        st.w = h2bits(v3);
        *(uint4*)&out[node * 128 + c] = st;
    }
}

// ---------------- GAT aggregation, layer 2 (1 head) ----------------
__global__ void __launch_bounds__(256, 6) att2_k(const __half* __restrict__ h,
                                                 const float* __restrict__ b,
                                                 float* __restrict__ out, int n) {
    __shared__ __align__(16) uint2 sm2[8][34];     // {src, half2(p,p)}
    int node = (blockIdx.x * blockDim.x + threadIdx.x) >> 5;
    int lane = threadIdx.x & 31;
    int ws = (threadIdx.x >> 5) & 7;
    if (node >= n) return;
    int s0 = g_rowptr[node], s1 = g_rowptr[node + 1];

    float ad = g_ad2[node];
    int hl = lane & 15, half = lane >> 4;
    float acc[8];
    #pragma unroll
    for (int i = 0; i < 8; i++) acc[i] = 0.f;
    float z = 0.f;

    for (int base = s0; base < s1; base += 32) {
        int j = base + lane;
        int s = 0; float p = 0.f;
        if (j < s1) {
            s = __ldg(&g_csr[j]);
            p = __expf(lrelu(g_as2[s] + ad));
            z += p;
        }
        __syncwarp();
        sm2[ws][lane] = make_uint2(s, h2bits(__floats2half2_rn(p, p)));
        __syncwarp();
        int cnt = min(32, s1 - base);
        int jb = half << 4;
        int je = min(cnt, jb + 16);
        int jj = jb;
        __half2 ha0 = bits2h(0u), ha1 = bits2h(0u), ha2 = bits2h(0u), ha3 = bits2h(0u);
        #pragma unroll 2
        for (; jj + 1 < je; jj += 2) {
            uint4 sp = *(const uint4*)&sm2[ws][jj];
            int sa = (int)sp.x;  __half2 qa = bits2h(sp.y);
            int sb = (int)sp.z;  __half2 qb = bits2h(sp.w);
            uint4 ua = *(const uint4*)&h[sa * 128 + (hl << 3)];
            uint4 ub = *(const uint4*)&h[sb * 128 + (hl << 3)];
            ha0 = __hfma2(bits2h(ua.x), qa, ha0);
            ha1 = __hfma2(bits2h(ua.y), qa, ha1);
            ha2 = __hfma2(bits2h(ua.z), qa, ha2);
            ha3 = __hfma2(bits2h(ua.w), qa, ha3);
            ha0 = __hfma2(bits2h(ub.x), qb, ha0);
            ha1 = __hfma2(bits2h(ub.y), qb, ha1);
            ha2 = __hfma2(bits2h(ub.z), qb, ha2);
            ha3 = __hfma2(bits2h(ub.w), qb, ha3);
        }
        if (jj < je) {
            uint2 sp = sm2[ws][jj];
            int sa = (int)sp.x;  __half2 qa = bits2h(sp.y);
            uint4 ua = *(const uint4*)&h[sa * 128 + (hl << 3)];
            ha0 = __hfma2(bits2h(ua.x), qa, ha0);
            ha1 = __hfma2(bits2h(ua.y), qa, ha1);
            ha2 = __hfma2(bits2h(ua.z), qa, ha2);
            ha3 = __hfma2(bits2h(ua.w), qa, ha3);
        }
        float2 f0 = __half22float2(ha0);
        float2 f1 = __half22float2(ha1);
        float2 f2 = __half22float2(ha2);
        float2 f3 = __half22float2(ha3);
        acc[0] += f0.x; acc[1] += f0.y;
        acc[2] += f1.x; acc[3] += f1.y;
        acc[4] += f2.x; acc[5] += f2.y;
        acc[6] += f3.x; acc[7] += f3.y;
    }
    #pragma unroll
    for (int i = 0; i < 8; i++) acc[i] += __shfl_xor_sync(FULL, acc[i], 16);
    #pragma unroll
    for (int off = 16; off; off >>= 1)
        z += __shfl_xor_sync(FULL, z, off);
    if (half == 0) {
        float inv = 1.f / z;
        int c = hl << 3;
        float4 b0 = *(const float4*)&b[c];
        float4 b1 = *(const float4*)&b[c + 4];
        float4 o0, o1;
        o0.x = elu(acc[0] * inv + b0.x);
        o0.y = elu(acc[1] * inv + b0.y);
        o0.z = elu(acc[2] * inv + b0.z);
        o0.w = elu(acc[3] * inv + b0.w);
        o1.x = elu(acc[4] * inv + b1.x);
        o1.y = elu(acc[5] * inv + b1.y);
        o1.z = elu(acc[6] * inv + b1.z);
        o1.w = elu(acc[7] * inv + b1.w);
        *(float4*)&out[node * 128 + c]     = o0;
        *(float4*)&out[node * 128 + c + 4] = o1;
    }
}

// ---------------- final linear head: [n,128] @ [128,40] + b ----------------
__global__ void head_k(const float* __restrict__ A, const float* __restrict__ W,
                       const float* __restrict__ b, float* __restrict__ out, int n) {
    int i = blockIdx.x * blockDim.x + threadIdx.x;
    if (i >= n * 40) return;
    int row = i / 40, c = i - row * 40;
    const float* xr = &A[row * 128];
    float acc = b[c];
    #pragma unroll 8
    for (int k = 0; k < 128; k++)
        acc += xr[k] * __ldg(&W[k * 40 + c]);
    out[i] = acc;
}

// ---------------- launch ----------------
extern "C" void kernel_launch(void* const* d_in, const int* in_sizes, int n_in,
                              void* d_out, int out_size) {
    const float* x   = (const float*)d_in[0];
    const int*   ei  = (const int*)  d_in[1];
    const float* W1  = (const float*)d_in[2];
    const float* as1 = (const float*)d_in[3];
    const float* ad1 = (const float*)d_in[4];
    const float* b1  = (const float*)d_in[5];
    const float* W2  = (const float*)d_in[6];
    const float* as2 = (const float*)d_in[7];
    const float* ad2 = (const float*)d_in[8];
    const float* b2  = (const float*)d_in[9];
    const float* Wl  = (const float*)d_in[10];
    const float* bl  = (const float*)d_in[11];
    float* out = (float*)d_out;

    const int n = in_sizes[0] / 128;   // 10000
    const int e = in_sizes[1] / 2;     // 640000

    __half *B1t, *B2t, *h1h, *h2h, *o1h;
    float *o2, *pas1, *pad1, *pas2, *pad2;
    cudaGetSymbolAddress((void**)&B1t, g_B1t);
    cudaGetSymbolAddress((void**)&B2t, g_B2t);
    cudaGetSymbolAddress((void**)&h1h, g_h1h);
    cudaGetSymbolAddress((void**)&h2h, g_h2h);
    cudaGetSymbolAddress((void**)&o1h, g_o1h);
    cudaGetSymbolAddress((void**)&o2,  g_o2);
    cudaGetSymbolAddress((void**)&pas1, g_as1);
    cudaGetSymbolAddress((void**)&pad1, g_ad1);
    cudaGetSymbolAddress((void**)&pas2, g_as2);
    cudaGetSymbolAddress((void**)&pad2, g_ad2);

    int q = e >> 2, tail = e & 3;

    // K1: hist + weight convert (independent; co-scheduled)
    int HB = (q + tail + 255) / 256;
    int WB = (2 * 128 * 128 / 4 + 255) / 256;
    combo1_k<<<HB + WB, 256>>>(ei, e, W1, W2, B1t, B2t, HB);

    // K2: scan (rowptr + self-loop slots + deg reset)
    scan_k<<<1, 1024>>>(n);

    // K3: fill + layer-1 GEMM (independent; co-scheduled)
    int FB = (q + tail + 127) / 128;
    int GB = (n + 15) / 16;
    combo2_k<<<FB + GB, 128>>>(ei, e, x, B1t, as1, ad1, h1h, pas1, pad1, n, FB);

    // K4: layer-1 aggregation
    att1_k<<<(n * 32 + 255) / 256, 256>>>(h1h, b1, o1h, n);

    // K5: layer-2 GEMM
    gemm2_k<<<(n + 15) / 16, 128>>>(o1h, B2t, as2, ad2, h2h, pas2, pad2, n);

    // K6: layer-2 aggregation
    att2_k<<<(n * 32 + 255) / 256, 256>>>(h2h, b2, o2, n);

    // K7: head
    head_k<<<(n * 40 + 255) / 256, 256>>>(o2, Wl, bl, out, n);
}